// round 1
// baseline (speedup 1.0000x reference)
#include <cuda_runtime.h>
#include <math.h>

#define NN   100000
#define NE   1600000
#define ET   (NE + NN)       // edges + self loops
#define FIN  165
#define HID  64
#define NCLS 2
#define NEG_SLOPE 0.2f

// ---------------- scratch (device globals; no allocations allowed) ----------
__device__ float g_h1[NN * HID];      // layer-1 linear output
__device__ float g_agg[NN * HID];     // layer-1 aggregation -> becomes h (relu'd)
__device__ float g_ssrc[NN];
__device__ float g_sdst[NN];
__device__ float g_emax[NN];
__device__ float g_den[NN];
__device__ float g_e[ET];             // per-edge e, then ee
__device__ float g_h2[NN * NCLS];
__device__ float g_s2s[NN];
__device__ float g_s2d[NN];
__device__ float g_emax2[NN];
__device__ float g_den2[NN];
__device__ float g_e2[ET];
__device__ float g_agg2[NN * NCLS];

// ---------------- helpers ---------------------------------------------------
__device__ __forceinline__ void atomicMaxF(float* addr, float val) {
    if (val >= 0.f) atomicMax((int*)addr, __float_as_int(val));
    else            atomicMin((unsigned int*)addr, __float_as_uint(val));
}

__device__ __forceinline__ void edge_sd(const int* __restrict__ ei, int idx,
                                        int& s, int& d) {
    if (idx < NE) { s = ei[idx]; d = ei[NE + idx]; }
    else          { s = idx - NE; d = idx - NE; }
}

// ---------------- init -------------------------------------------------------
__global__ void k_init() {
    int i = blockIdx.x * blockDim.x + threadIdx.x;
    if (i < NN * HID) g_agg[i] = 0.f;
    if (i < NN) {
        g_emax[i]  = -INFINITY; g_den[i]  = 0.f;
        g_emax2[i] = -INFINITY; g_den2[i] = 0.f;
    }
    if (i < NN * NCLS) g_agg2[i] = 0.f;
}

// ---------------- GEMM1: h1 = x @ W1  (100000x165 @ 165x64) -----------------
#define BM 64
#define BN 64
#define BK 33   // 165 = 5 * 33
__global__ void k_gemm1(const float* __restrict__ x, const float* __restrict__ W) {
    __shared__ float As[BM][BK + 1];
    __shared__ float Bs[BK][BN];
    const int block_row = blockIdx.x * BM;
    const int tid  = threadIdx.x;          // 256
    const int tcol = tid & 15;
    const int trow = tid >> 4;
    float acc[4][4] = {};

    for (int kt = 0; kt < FIN; kt += BK) {
        for (int i = tid; i < BM * BK; i += 256) {
            int r = i / BK, k = i % BK;
            int row = block_row + r;
            As[r][k] = (row < NN) ? x[(size_t)row * FIN + kt + k] : 0.f;
        }
        for (int i = tid; i < BK * BN; i += 256) {
            int k = i / BN, c = i % BN;
            Bs[k][c] = W[(size_t)(kt + k) * BN + c];
        }
        __syncthreads();
#pragma unroll
        for (int k = 0; k < BK; k++) {
            float a[4], b[4];
#pragma unroll
            for (int r = 0; r < 4; r++) a[r] = As[trow * 4 + r][k];
#pragma unroll
            for (int c = 0; c < 4; c++) b[c] = Bs[k][tcol * 4 + c];
#pragma unroll
            for (int r = 0; r < 4; r++)
#pragma unroll
                for (int c = 0; c < 4; c++) acc[r][c] = fmaf(a[r], b[c], acc[r][c]);
        }
        __syncthreads();
    }
#pragma unroll
    for (int r = 0; r < 4; r++) {
        int row = block_row + trow * 4 + r;
        if (row < NN)
#pragma unroll
            for (int c = 0; c < 4; c++)
                g_h1[(size_t)row * HID + tcol * 4 + c] = acc[r][c];
    }
}

// ---------------- per-node attention scores (layer 1) ------------------------
__global__ void k_scores1(const float* __restrict__ a_s, const float* __restrict__ a_d) {
    int warp = (blockIdx.x * blockDim.x + threadIdx.x) >> 5;
    int lane = threadIdx.x & 31;
    if (warp >= NN) return;
    const float* h = g_h1 + (size_t)warp * HID;
    float v0 = h[lane], v1 = h[lane + 32];
    float s1 = v0 * a_s[lane] + v1 * a_s[lane + 32];
    float s2 = v0 * a_d[lane] + v1 * a_d[lane + 32];
#pragma unroll
    for (int o = 16; o; o >>= 1) {
        s1 += __shfl_down_sync(0xffffffffu, s1, o);
        s2 += __shfl_down_sync(0xffffffffu, s2, o);
    }
    if (lane == 0) { g_ssrc[warp] = s1; g_sdst[warp] = s2; }
}

// ---------------- edge pass 1: e = leakyrelu, segment max --------------------
__global__ void k_edge1_max(const int* __restrict__ ei) {
    int idx = blockIdx.x * blockDim.x + threadIdx.x;
    if (idx >= ET) return;
    int s, d; edge_sd(ei, idx, s, d);
    float e = g_ssrc[s] + g_sdst[d];
    e = (e > 0.f) ? e : NEG_SLOPE * e;
    g_e[idx] = e;
    atomicMaxF(&g_emax[d], e);
}

// ---------------- edge pass 2: ee = exp(e - emax), denom sum -----------------
__global__ void k_edge1_exp(const int* __restrict__ ei) {
    int idx = blockIdx.x * blockDim.x + threadIdx.x;
    if (idx >= ET) return;
    int s, d; edge_sd(ei, idx, s, d);
    float ee = __expf(g_e[idx] - g_emax[d]);
    g_e[idx] = ee;
    atomicAdd(&g_den[d], ee);
}

// ---------------- edge pass 3: weighted aggregation (warp per edge) ----------
__global__ void k_edge1_agg(const int* __restrict__ ei) {
    int widx = (blockIdx.x * blockDim.x + threadIdx.x) >> 5;
    int lane = threadIdx.x & 31;
    if (widx >= ET) return;
    int s, d; edge_sd(ei, widx, s, d);
    float alpha = g_e[widx] / g_den[d];
    const float* h = g_h1 + (size_t)s * HID;
    float* o = g_agg + (size_t)d * HID;
    atomicAdd(&o[lane],      alpha * h[lane]);
    atomicAdd(&o[lane + 32], alpha * h[lane + 32]);
}

// ---------------- bias + relu (in place: g_agg becomes layer-2 input) --------
__global__ void k_bias_relu(const float* __restrict__ b1) {
    int i = blockIdx.x * blockDim.x + threadIdx.x;
    if (i >= NN * HID) return;
    float v = g_agg[i] + b1[i & (HID - 1)];
    g_agg[i] = (v > 0.f) ? v : 0.f;
}

// ---------------- GEMM2 + layer-2 scores (warp per node) ---------------------
__global__ void k_gemm2_scores(const float* __restrict__ W2,
                               const float* __restrict__ a2s,
                               const float* __restrict__ a2d) {
    int node = (blockIdx.x * blockDim.x + threadIdx.x) >> 5;
    int lane = threadIdx.x & 31;
    if (node >= NN) return;
    const float* h = g_agg + (size_t)node * HID;
    float h0 = h[lane], h1v = h[lane + 32];
    float c0 = h0 * W2[lane * 2 + 0] + h1v * W2[(lane + 32) * 2 + 0];
    float c1 = h0 * W2[lane * 2 + 1] + h1v * W2[(lane + 32) * 2 + 1];
#pragma unroll
    for (int o = 16; o; o >>= 1) {
        c0 += __shfl_down_sync(0xffffffffu, c0, o);
        c1 += __shfl_down_sync(0xffffffffu, c1, o);
    }
    if (lane == 0) {
        g_h2[node * 2 + 0] = c0;
        g_h2[node * 2 + 1] = c1;
        g_s2s[node] = c0 * a2s[0] + c1 * a2s[1];
        g_s2d[node] = c0 * a2d[0] + c1 * a2d[1];
    }
}

// ---------------- layer-2 edge passes ---------------------------------------
__global__ void k_edge2_max(const int* __restrict__ ei) {
    int idx = blockIdx.x * blockDim.x + threadIdx.x;
    if (idx >= ET) return;
    int s, d; edge_sd(ei, idx, s, d);
    float e = g_s2s[s] + g_s2d[d];
    e = (e > 0.f) ? e : NEG_SLOPE * e;
    g_e2[idx] = e;
    atomicMaxF(&g_emax2[d], e);
}

__global__ void k_edge2_exp(const int* __restrict__ ei) {
    int idx = blockIdx.x * blockDim.x + threadIdx.x;
    if (idx >= ET) return;
    int s, d; edge_sd(ei, idx, s, d);
    float ee = __expf(g_e2[idx] - g_emax2[d]);
    g_e2[idx] = ee;
    atomicAdd(&g_den2[d], ee);
}

__global__ void k_edge2_agg(const int* __restrict__ ei) {
    int idx = blockIdx.x * blockDim.x + threadIdx.x;
    if (idx >= ET) return;
    int s, d; edge_sd(ei, idx, s, d);
    float alpha = g_e2[idx] / g_den2[d];
    atomicAdd(&g_agg2[d * 2 + 0], alpha * g_h2[s * 2 + 0]);
    atomicAdd(&g_agg2[d * 2 + 1], alpha * g_h2[s * 2 + 1]);
}

// ---------------- finalize ----------------------------------------------------
__global__ void k_final(float* __restrict__ out, const float* __restrict__ b2) {
    int i = blockIdx.x * blockDim.x + threadIdx.x;
    if (i >= NN * NCLS) return;
    out[i] = g_agg2[i] + b2[i & 1];
}

__global__ void k_copy_edges(float* __restrict__ out, const int* __restrict__ ei) {
    int i = blockIdx.x * blockDim.x + threadIdx.x;
    if (i >= 2 * NE) return;
    out[NN * NCLS + i] = (float)ei[i];
}

// ---------------- launch ------------------------------------------------------
extern "C" void kernel_launch(void* const* d_in, const int* in_sizes, int n_in,
                              void* d_out, int out_size) {
    const float* x    = (const float*)d_in[0];
    const int*   ei   = (const int*)  d_in[1];
    const float* W1   = (const float*)d_in[2];
    const float* a1s  = (const float*)d_in[3];
    const float* a1d  = (const float*)d_in[4];
    const float* b1   = (const float*)d_in[5];
    const float* W2   = (const float*)d_in[6];
    const float* a2s  = (const float*)d_in[7];
    const float* a2d  = (const float*)d_in[8];
    const float* b2   = (const float*)d_in[9];
    float* out = (float*)d_out;

    const int T = 256;
    k_init<<<(NN * HID + T - 1) / T, T>>>();
    k_gemm1<<<(NN + BM - 1) / BM, 256>>>(x, W1);
    k_scores1<<<(NN * 32 + T - 1) / T, T>>>(a1s, a1d);
    k_edge1_max<<<(ET + T - 1) / T, T>>>(ei);
    k_edge1_exp<<<(ET + T - 1) / T, T>>>(ei);
    k_edge1_agg<<<((size_t)ET * 32 + T - 1) / T, T>>>(ei);
    k_bias_relu<<<(NN * HID + T - 1) / T, T>>>(b1);
    k_gemm2_scores<<<(NN * 32 + T - 1) / T, T>>>(W2, a2s, a2d);
    k_edge2_max<<<(ET + T - 1) / T, T>>>(ei);
    k_edge2_exp<<<(ET + T - 1) / T, T>>>(ei);
    k_edge2_agg<<<(ET + T - 1) / T, T>>>(ei);
    k_final<<<(NN * NCLS + T - 1) / T, T>>>(out, b2);
    if (out_size >= NN * NCLS + 2 * NE)
        k_copy_edges<<<(2 * NE + T - 1) / T, T>>>(out, ei);
}

// round 3
// speedup vs baseline: 1.7026x; 1.7026x over previous
#include <cuda_runtime.h>
#include <math.h>

#define NN   100000
#define NE   1600000
#define FIN  165
#define HID  64
#define NCLS 2
#define NEG_SLOPE 0.2f

#define SCAN_BLK 1024
#define NB ((NN + 1 + SCAN_BLK - 1) / SCAN_BLK)   // 98 blocks for NN+1 entries

// ---------------- scratch (device globals; no allocations allowed) ----------
__device__ float g_h1[NN * HID];      // layer-1 linear output
__device__ float g_h [NN * HID];      // layer-1 output (post agg+bias+relu)
__device__ float g_ssrc[NN];
__device__ float g_sdst[NN];
__device__ float g_h2[NN * NCLS];
__device__ float g_s2s[NN];
__device__ float g_s2d[NN];
__device__ int   g_deg[NN + 1];       // hist -> in-place local exclusive scan
__device__ int   g_bsum[128];
__device__ int   g_rowstart[NN + 1];
__device__ int   g_cursor[NN];
__device__ int   g_csr_src[NE];

// ---------------- helpers ---------------------------------------------------
__device__ __forceinline__ float lrelu(float x) {
    return (x > 0.f) ? x : NEG_SLOPE * x;
}

// ---------------- zero degree ------------------------------------------------
__global__ void k_zero_deg() {
    int i = blockIdx.x * blockDim.x + threadIdx.x;
    if (i <= NN) g_deg[i] = 0;
}

// ---------------- GEMM1: h1 = x @ W1  (100000x165 @ 165x64) ------------------
#define BM 128
#define BN 64
#define BK 33   // 165 = 5 * 33
__global__ void k_gemm1(const float* __restrict__ x, const float* __restrict__ W) {
    __shared__ float As[BM][BK + 1];
    __shared__ float Bs[BK][BN];
    const int block_row = blockIdx.x * BM;
    const int tid  = threadIdx.x;          // 256
    const int tcol = tid & 15;             // 16 col groups of 4
    const int trow = tid >> 4;             // 16 row groups of 8
    float acc[8][4] = {};

    for (int kt = 0; kt < FIN; kt += BK) {
        for (int i = tid; i < BM * BK; i += 256) {
            int r = i / BK, k = i % BK;
            int row = block_row + r;
            As[r][k] = (row < NN) ? x[(size_t)row * FIN + kt + k] : 0.f;
        }
        for (int i = tid; i < BK * BN; i += 256) {
            int k = i / BN, c = i % BN;
            Bs[k][c] = W[(size_t)(kt + k) * BN + c];
        }
        __syncthreads();
#pragma unroll
        for (int k = 0; k < BK; k++) {
            float a[8];
#pragma unroll
            for (int r = 0; r < 8; r++) a[r] = As[trow * 8 + r][k];
            float4 b4 = *(const float4*)&Bs[k][tcol * 4];
            float b[4] = {b4.x, b4.y, b4.z, b4.w};
#pragma unroll
            for (int r = 0; r < 8; r++)
#pragma unroll
                for (int c = 0; c < 4; c++) acc[r][c] = fmaf(a[r], b[c], acc[r][c]);
        }
        __syncthreads();
    }
#pragma unroll
    for (int r = 0; r < 8; r++) {
        int row = block_row + trow * 8 + r;
        if (row < NN) {
            float4 v = make_float4(acc[r][0], acc[r][1], acc[r][2], acc[r][3]);
            *(float4*)&g_h1[(size_t)row * HID + tcol * 4] = v;
        }
    }
}

// ---------------- per-node attention scores (layer 1) ------------------------
__global__ void k_scores1(const float* __restrict__ a_s, const float* __restrict__ a_d) {
    int warp = (blockIdx.x * blockDim.x + threadIdx.x) >> 5;
    int lane = threadIdx.x & 31;
    if (warp >= NN) return;
    const float* h = g_h1 + (size_t)warp * HID;
    float v0 = h[lane], v1 = h[lane + 32];
    float s1 = v0 * a_s[lane] + v1 * a_s[lane + 32];
    float s2 = v0 * a_d[lane] + v1 * a_d[lane + 32];
#pragma unroll
    for (int o = 16; o; o >>= 1) {
        s1 += __shfl_down_sync(0xffffffffu, s1, o);
        s2 += __shfl_down_sync(0xffffffffu, s2, o);
    }
    if (lane == 0) { g_ssrc[warp] = s1; g_sdst[warp] = s2; }
}

// ---------------- CSR build: hist -> scan -> scatter -------------------------
__global__ void k_hist(const int* __restrict__ ei) {
    int i = blockIdx.x * blockDim.x + threadIdx.x;
    if (i >= NE) return;
    atomicAdd(&g_deg[ei[NE + i]], 1);
}

__global__ void k_scan_local() {
    __shared__ int warp_sums[32];
    int i = blockIdx.x * SCAN_BLK + threadIdx.x;
    int lane = threadIdx.x & 31, wid = threadIdx.x >> 5;
    int v = (i <= NN) ? g_deg[i] : 0;
    int xv = v;
#pragma unroll
    for (int o = 1; o < 32; o <<= 1) {
        int y = __shfl_up_sync(0xffffffffu, xv, o);
        if (lane >= o) xv += y;
    }
    if (lane == 31) warp_sums[wid] = xv;
    __syncthreads();
    if (wid == 0) {
        int s = warp_sums[lane];
#pragma unroll
        for (int o = 1; o < 32; o <<= 1) {
            int y = __shfl_up_sync(0xffffffffu, s, o);
            if (lane >= o) s += y;
        }
        warp_sums[lane] = s;
    }
    __syncthreads();
    int base = wid ? warp_sums[wid - 1] : 0;
    int incl = xv + base;
    if (i <= NN) g_deg[i] = incl - v;          // local exclusive scan, in place
    if (threadIdx.x == SCAN_BLK - 1) g_bsum[blockIdx.x] = incl;
}

__global__ void k_scan_bsum() {            // 1 block, 128 threads, NB<=128
    __shared__ int warp_sums[4];
    int t = threadIdx.x;
    int lane = t & 31, wid = t >> 5;
    int v = (t < NB) ? g_bsum[t] : 0;
    int xv = v;
#pragma unroll
    for (int o = 1; o < 32; o <<= 1) {
        int y = __shfl_up_sync(0xffffffffu, xv, o);
        if (lane >= o) xv += y;
    }
    if (lane == 31) warp_sums[wid] = xv;
    __syncthreads();
    int base = 0;
    for (int w = 0; w < wid; w++) base += warp_sums[w];
    g_bsum[t] = xv - v + base;             // exclusive
}

__global__ void k_scan_add() {
    int i = blockIdx.x * blockDim.x + threadIdx.x;
    if (i > NN) return;
    int rs = g_deg[i] + g_bsum[i >> 10];
    g_rowstart[i] = rs;
    if (i < NN) g_cursor[i] = rs;
}

__global__ void k_scatter(const int* __restrict__ ei) {
    int i = blockIdx.x * blockDim.x + threadIdx.x;
    if (i >= NE) return;
    int s = ei[i], d = ei[NE + i];
    int pos = atomicAdd(&g_cursor[d], 1);
    g_csr_src[pos] = s;
}

// ---------------- layer-1 fused: softmax-denom + aggregate + bias + relu -----
__global__ void k_l1agg(const float* __restrict__ b1) {
    int node = (blockIdx.x * blockDim.x + threadIdx.x) >> 5;
    int lane = threadIdx.x & 31;
    if (node >= NN) return;
    int start = g_rowstart[node], end = g_rowstart[node + 1];
    float sd = g_sdst[node];
    // self loop contribution
    float ee = __expf(lrelu(g_ssrc[node] + sd));
    float den = ee;
    const float* hself = g_h1 + (size_t)node * HID;
    float a0 = ee * hself[lane];
    float a1 = ee * hself[lane + 32];
    for (int j = start; j < end; j++) {
        int s = g_csr_src[j];                     // warp-broadcast load
        float e = __expf(lrelu(g_ssrc[s] + sd));  // warp-broadcast load
        den += e;
        const float* hs = g_h1 + (size_t)s * HID;
        a0 = fmaf(e, hs[lane],      a0);
        a1 = fmaf(e, hs[lane + 32], a1);
    }
    float inv = 1.f / den;
    float v0 = a0 * inv + b1[lane];
    float v1 = a1 * inv + b1[lane + 32];
    g_h[(size_t)node * HID + lane]      = fmaxf(v0, 0.f);
    g_h[(size_t)node * HID + lane + 32] = fmaxf(v1, 0.f);
}

// ---------------- GEMM2 + layer-2 scores (warp per node) ---------------------
__global__ void k_gemm2_scores(const float* __restrict__ W2,
                               const float* __restrict__ a2s,
                               const float* __restrict__ a2d) {
    int node = (blockIdx.x * blockDim.x + threadIdx.x) >> 5;
    int lane = threadIdx.x & 31;
    if (node >= NN) return;
    const float* h = g_h + (size_t)node * HID;
    float h0 = h[lane], h1v = h[lane + 32];
    float c0 = h0 * W2[lane * 2 + 0] + h1v * W2[(lane + 32) * 2 + 0];
    float c1 = h0 * W2[lane * 2 + 1] + h1v * W2[(lane + 32) * 2 + 1];
#pragma unroll
    for (int o = 16; o; o >>= 1) {
        c0 += __shfl_down_sync(0xffffffffu, c0, o);
        c1 += __shfl_down_sync(0xffffffffu, c1, o);
    }
    if (lane == 0) {
        g_h2[node * 2 + 0] = c0;
        g_h2[node * 2 + 1] = c1;
        g_s2s[node] = c0 * a2s[0] + c1 * a2s[1];
        g_s2d[node] = c0 * a2d[0] + c1 * a2d[1];
    }
}

// ---------------- layer-2 fused: denom + aggregate + bias -> out -------------
__global__ void k_l2agg(float* __restrict__ out, const float* __restrict__ b2) {
    int node = (blockIdx.x * blockDim.x + threadIdx.x) >> 5;
    int lane = threadIdx.x & 31;
    if (node >= NN) return;
    int start = g_rowstart[node], end = g_rowstart[node + 1];
    float sd = g_s2d[node];
    float den = 0.f, a0 = 0.f, a1 = 0.f;
    for (int j = start + lane; j < end; j += 32) {
        int s = g_csr_src[j];
        float ee = __expf(lrelu(g_s2s[s] + sd));
        den += ee;
        float2 h2 = *((const float2*)g_h2 + s);
        a0 = fmaf(ee, h2.x, a0);
        a1 = fmaf(ee, h2.y, a1);
    }
#pragma unroll
    for (int o = 16; o; o >>= 1) {
        den += __shfl_xor_sync(0xffffffffu, den, o);
        a0  += __shfl_xor_sync(0xffffffffu, a0,  o);
        a1  += __shfl_xor_sync(0xffffffffu, a1,  o);
    }
    if (lane == 0) {
        float ee = __expf(lrelu(g_s2s[node] + sd));   // self loop
        den += ee;
        float2 h2 = *((const float2*)g_h2 + node);
        a0 = fmaf(ee, h2.x, a0);
        a1 = fmaf(ee, h2.y, a1);
        float inv = 1.f / den;
        out[node * 2 + 0] = a0 * inv + b2[0];
        out[node * 2 + 1] = a1 * inv + b2[1];
    }
}

// ---------------- edge echo ---------------------------------------------------
__global__ void k_copy_edges(float* __restrict__ out, const int* __restrict__ ei) {
    int i = blockIdx.x * blockDim.x + threadIdx.x;
    if (i >= 2 * NE) return;
    out[NN * NCLS + i] = (float)ei[i];
}

// ---------------- launch ------------------------------------------------------
extern "C" void kernel_launch(void* const* d_in, const int* in_sizes, int n_in,
                              void* d_out, int out_size) {
    const float* x    = (const float*)d_in[0];
    const int*   ei   = (const int*)  d_in[1];
    const float* W1   = (const float*)d_in[2];
    const float* a1s  = (const float*)d_in[3];
    const float* a1d  = (const float*)d_in[4];
    const float* b1   = (const float*)d_in[5];
    const float* W2   = (const float*)d_in[6];
    const float* a2s  = (const float*)d_in[7];
    const float* a2d  = (const float*)d_in[8];
    const float* b2   = (const float*)d_in[9];
    float* out = (float*)d_out;

    const int T = 256;
    k_zero_deg<<<(NN + 1 + T - 1) / T, T>>>();
    k_hist<<<(NE + T - 1) / T, T>>>(ei);
    k_gemm1<<<(NN + BM - 1) / BM, 256>>>(x, W1);
    k_scan_local<<<NB, SCAN_BLK>>>();
    k_scan_bsum<<<1, 128>>>();
    k_scan_add<<<(NN + 1 + T - 1) / T, T>>>();
    k_scatter<<<(NE + T - 1) / T, T>>>(ei);
    k_scores1<<<(NN * 32 + T - 1) / T, T>>>(a1s, a1d);
    k_l1agg<<<(NN * 32 + T - 1) / T, T>>>(b1);
    k_gemm2_scores<<<(NN * 32 + T - 1) / T, T>>>(W2, a2s, a2d);
    k_l2agg<<<(NN * 32 + T - 1) / T, T>>>(out, b2);
    if (out_size >= NN * NCLS + 2 * NE)
        k_copy_edges<<<(2 * NE + T - 1) / T, T>>>(out, ei);
}

// round 5
// speedup vs baseline: 2.0161x; 1.1842x over previous
#include <cuda_runtime.h>
#include <math.h>

#define NN   100000
#define NE   1600000
#define FIN  165
#define HID  64
#define NCLS 2
#define NEG_SLOPE 0.2f

#define SCAN_BLK 1024
#define NB ((NN + 1 + SCAN_BLK - 1) / SCAN_BLK)   // 98 blocks for NN+1 entries

// ---------------- scratch (device globals; no allocations allowed) ----------
__device__ float g_h1[NN * HID];      // layer-1 linear output
__device__ float g_ssrc[NN];
__device__ float g_sdst[NN];
__device__ float g_h2[NN * NCLS];
__device__ float g_s2s[NN];
__device__ float g_s2d[NN];
__device__ int   g_deg[NN + 1];       // hist -> in-place local exclusive scan
__device__ int   g_bsum[128];
__device__ int   g_rowstart[NN + 1];
__device__ int   g_cursor[NN];
__device__ int2  g_csr[NE];           // {src, exp-score bits} per edge, dst-grouped

// ---------------- helpers ---------------------------------------------------
__device__ __forceinline__ float lrelu(float x) {
    return (x > 0.f) ? x : NEG_SLOPE * x;
}

// ---------------- zero degree ------------------------------------------------
__global__ void k_zero_deg() {
    int i = blockIdx.x * blockDim.x + threadIdx.x;
    if (i <= NN) g_deg[i] = 0;
}

// ---------------- GEMM1: h1 = x @ W1  (100000x165 @ 165x64) ------------------
// 128 threads/block, tile 128x64, micro-tile 8x8 (16 LDS per 64 FMA: balanced)
#define BM 128
#define BN 64
#define BK 33   // 165 = 5 * 33
__global__ void __launch_bounds__(128) k_gemm1(const float* __restrict__ x,
                                               const float* __restrict__ W) {
    __shared__ float As[BM][BK + 1];
    __shared__ float Bs[BK][BN];
    const int block_row = blockIdx.x * BM;
    const int tid = threadIdx.x;          // 128
    const int tc  = tid & 7;              // 8 col groups of 8
    const int tr  = tid >> 3;             // 16 row groups of 8
    float acc[8][8] = {};

    for (int kt = 0; kt < FIN; kt += BK) {
        for (int i = tid; i < BM * BK; i += 128) {
            int r = i / BK, k = i - r * BK;
            int row = block_row + r;
            As[r][k] = (row < NN) ? x[(size_t)row * FIN + kt + k] : 0.f;
        }
        for (int i = tid; i < BK * BN; i += 128) {
            int k = i >> 6, c = i & 63;
            Bs[k][c] = W[(size_t)(kt + k) * BN + c];
        }
        __syncthreads();
#pragma unroll
        for (int k = 0; k < BK; k++) {
            float a[8], b[8];
#pragma unroll
            for (int r = 0; r < 8; r++) a[r] = As[tr * 8 + r][k];
            float4 blo = *(const float4*)&Bs[k][tc * 8];
            float4 bhi = *(const float4*)&Bs[k][tc * 8 + 4];
            b[0] = blo.x; b[1] = blo.y; b[2] = blo.z; b[3] = blo.w;
            b[4] = bhi.x; b[5] = bhi.y; b[6] = bhi.z; b[7] = bhi.w;
#pragma unroll
            for (int r = 0; r < 8; r++)
#pragma unroll
                for (int c = 0; c < 8; c++) acc[r][c] = fmaf(a[r], b[c], acc[r][c]);
        }
        __syncthreads();
    }
#pragma unroll
    for (int r = 0; r < 8; r++) {
        int row = block_row + tr * 8 + r;
        if (row < NN) {
            *(float4*)&g_h1[(size_t)row * HID + tc * 8] =
                make_float4(acc[r][0], acc[r][1], acc[r][2], acc[r][3]);
            *(float4*)&g_h1[(size_t)row * HID + tc * 8 + 4] =
                make_float4(acc[r][4], acc[r][5], acc[r][6], acc[r][7]);
        }
    }
}

// ---------------- per-node attention scores (layer 1) ------------------------
__global__ void k_scores1(const float* __restrict__ a_s, const float* __restrict__ a_d) {
    int warp = (blockIdx.x * blockDim.x + threadIdx.x) >> 5;
    int lane = threadIdx.x & 31;
    if (warp >= NN) return;
    const float* h = g_h1 + (size_t)warp * HID;
    float v0 = h[lane], v1 = h[lane + 32];
    float s1 = v0 * a_s[lane] + v1 * a_s[lane + 32];
    float s2 = v0 * a_d[lane] + v1 * a_d[lane + 32];
#pragma unroll
    for (int o = 16; o; o >>= 1) {
        s1 += __shfl_down_sync(0xffffffffu, s1, o);
        s2 += __shfl_down_sync(0xffffffffu, s2, o);
    }
    if (lane == 0) { g_ssrc[warp] = s1; g_sdst[warp] = s2; }
}

// ---------------- CSR build: hist -> scan -> scatter -------------------------
__global__ void k_hist(const int* __restrict__ ei) {
    int i = blockIdx.x * blockDim.x + threadIdx.x;
    if (i >= NE) return;
    atomicAdd(&g_deg[ei[NE + i]], 1);
}

__global__ void k_scan_local() {
    __shared__ int warp_sums[32];
    int i = blockIdx.x * SCAN_BLK + threadIdx.x;
    int lane = threadIdx.x & 31, wid = threadIdx.x >> 5;
    int v = (i <= NN) ? g_deg[i] : 0;
    int xv = v;
#pragma unroll
    for (int o = 1; o < 32; o <<= 1) {
        int y = __shfl_up_sync(0xffffffffu, xv, o);
        if (lane >= o) xv += y;
    }
    if (lane == 31) warp_sums[wid] = xv;
    __syncthreads();
    if (wid == 0) {
        int s = warp_sums[lane];
#pragma unroll
        for (int o = 1; o < 32; o <<= 1) {
            int y = __shfl_up_sync(0xffffffffu, s, o);
            if (lane >= o) s += y;
        }
        warp_sums[lane] = s;
    }
    __syncthreads();
    int base = wid ? warp_sums[wid - 1] : 0;
    int incl = xv + base;
    if (i <= NN) g_deg[i] = incl - v;          // local exclusive scan, in place
    if (threadIdx.x == SCAN_BLK - 1) g_bsum[blockIdx.x] = incl;
}

__global__ void k_scan_bsum() {            // 1 block, 128 threads, NB<=128
    __shared__ int warp_sums[4];
    int t = threadIdx.x;
    int lane = t & 31, wid = t >> 5;
    int v = (t < NB) ? g_bsum[t] : 0;
    int xv = v;
#pragma unroll
    for (int o = 1; o < 32; o <<= 1) {
        int y = __shfl_up_sync(0xffffffffu, xv, o);
        if (lane >= o) xv += y;
    }
    if (lane == 31) warp_sums[wid] = xv;
    __syncthreads();
    int base = 0;
    for (int w = 0; w < wid; w++) base += warp_sums[w];
    g_bsum[t] = xv - v + base;             // exclusive
}

__global__ void k_scan_add() {
    int i = blockIdx.x * blockDim.x + threadIdx.x;
    if (i > NN) return;
    int rs = g_deg[i] + g_bsum[i >> 10];
    g_rowstart[i] = rs;
    if (i < NN) g_cursor[i] = rs;
}

// scatter also precomputes the per-edge softmax numerator for layer 1
__global__ void k_scatter(const int* __restrict__ ei) {
    int i = blockIdx.x * blockDim.x + threadIdx.x;
    if (i >= NE) return;
    int s = ei[i], d = ei[NE + i];
    float e = __expf(lrelu(g_ssrc[s] + g_sdst[d]));
    int pos = atomicAdd(&g_cursor[d], 1);
    g_csr[pos] = make_int2(s, __float_as_int(e));
}

// ---------------- layer-1 fused: agg + bias + relu + GEMM2 + scores2 --------
__global__ void k_l1agg(const float* __restrict__ b1,
                        const float* __restrict__ W2,
                        const float* __restrict__ a2s,
                        const float* __restrict__ a2d) {
    int node = (blockIdx.x * blockDim.x + threadIdx.x) >> 5;
    int lane = threadIdx.x & 31;
    if (node >= NN) return;
    int start = g_rowstart[node], end = g_rowstart[node + 1];
    // self loop contribution
    float ee = __expf(lrelu(g_ssrc[node] + g_sdst[node]));
    float den = ee;
    const float* hself = g_h1 + (size_t)node * HID;
    float a0 = ee * hself[lane];
    float a1 = ee * hself[lane + 32];
    for (int j = start; j < end; j++) {
        int2 se = g_csr[j];                     // warp-broadcast 8B load
        float e = __int_as_float(se.y);
        den += e;
        const float* hs = g_h1 + (size_t)se.x * HID;
        a0 = fmaf(e, hs[lane],      a0);
        a1 = fmaf(e, hs[lane + 32], a1);
    }
    float inv = 1.f / den;
    float v0 = fmaxf(a0 * inv + b1[lane],      0.f);   // relu'd h, lanes 0..31
    float v1 = fmaxf(a1 * inv + b1[lane + 32], 0.f);   // relu'd h, lanes 32..63
    // fused layer-2 linear: c = h @ W2  (HID x 2)
    float c0 = v0 * W2[lane * 2 + 0] + v1 * W2[(lane + 32) * 2 + 0];
    float c1 = v0 * W2[lane * 2 + 1] + v1 * W2[(lane + 32) * 2 + 1];
#pragma unroll
    for (int o = 16; o; o >>= 1) {
        c0 += __shfl_down_sync(0xffffffffu, c0, o);
        c1 += __shfl_down_sync(0xffffffffu, c1, o);
    }
    if (lane == 0) {
        g_h2[node * 2 + 0] = c0;
        g_h2[node * 2 + 1] = c1;
        g_s2s[node] = c0 * a2s[0] + c1 * a2s[1];
        g_s2d[node] = c0 * a2d[0] + c1 * a2d[1];
    }
}

// ---------------- layer-2 fused: denom + aggregate + bias -> out -------------
__global__ void k_l2agg(float* __restrict__ out, const float* __restrict__ b2) {
    int node = (blockIdx.x * blockDim.x + threadIdx.x) >> 5;
    int lane = threadIdx.x & 31;
    if (node >= NN) return;
    int start = g_rowstart[node], end = g_rowstart[node + 1];
    float sd = g_s2d[node];
    float den = 0.f, a0 = 0.f, a1 = 0.f;
    for (int j = start + lane; j < end; j += 32) {
        int s = g_csr[j].x;
        float ee = __expf(lrelu(g_s2s[s] + sd));
        den += ee;
        float2 h2 = *((const float2*)g_h2 + s);
        a0 = fmaf(ee, h2.x, a0);
        a1 = fmaf(ee, h2.y, a1);
    }
#pragma unroll
    for (int o = 16; o; o >>= 1) {
        den += __shfl_xor_sync(0xffffffffu, den, o);
        a0  += __shfl_xor_sync(0xffffffffu, a0,  o);
        a1  += __shfl_xor_sync(0xffffffffu, a1,  o);
    }
    if (lane == 0) {
        float ee = __expf(lrelu(g_s2s[node] + sd));   // self loop
        den += ee;
        float2 h2 = *((const float2*)g_h2 + node);
        a0 = fmaf(ee, h2.x, a0);
        a1 = fmaf(ee, h2.y, a1);
        float inv = 1.f / den;
        out[node * 2 + 0] = a0 * inv + b2[0];
        out[node * 2 + 1] = a1 * inv + b2[1];
    }
}

// ---------------- edge echo (vectorized) -------------------------------------
__global__ void k_copy_edges(float* __restrict__ out, const int* __restrict__ ei) {
    int i = blockIdx.x * blockDim.x + threadIdx.x;   // one int4 per thread
    if (i >= (2 * NE) / 4) return;
    int4 v = ((const int4*)ei)[i];
    ((float4*)(out + NN * NCLS))[i] =
        make_float4((float)v.x, (float)v.y, (float)v.z, (float)v.w);
}

// ---------------- launch ------------------------------------------------------
extern "C" void kernel_launch(void* const* d_in, const int* in_sizes, int n_in,
                              void* d_out, int out_size) {
    const float* x    = (const float*)d_in[0];
    const int*   ei   = (const int*)  d_in[1];
    const float* W1   = (const float*)d_in[2];
    const float* a1s  = (const float*)d_in[3];
    const float* a1d  = (const float*)d_in[4];
    const float* b1   = (const float*)d_in[5];
    const float* W2   = (const float*)d_in[6];
    const float* a2s  = (const float*)d_in[7];
    const float* a2d  = (const float*)d_in[8];
    const float* b2   = (const float*)d_in[9];
    float* out = (float*)d_out;

    const int T = 256;
    k_zero_deg<<<(NN + 1 + T - 1) / T, T>>>();
    k_hist<<<(NE + T - 1) / T, T>>>(ei);
    k_scan_local<<<NB, SCAN_BLK>>>();
    k_scan_bsum<<<1, 128>>>();
    k_scan_add<<<(NN + 1 + T - 1) / T, T>>>();
    k_gemm1<<<(NN + BM - 1) / BM, 128>>>(x, W1);
    k_scores1<<<(NN * 32 + T - 1) / T, T>>>(a1s, a1d);
    k_scatter<<<(NE + T - 1) / T, T>>>(ei);
    k_l1agg<<<(NN * 32 + T - 1) / T, T>>>(b1, W2, a2s, a2d);
    k_l2agg<<<(NN * 32 + T - 1) / T, T>>>(out, b2);
    if (out_size >= NN * NCLS + 2 * NE)
        k_copy_edges<<<((2 * NE) / 4 + T - 1) / T, T>>>(out, ei);
}